// round 12
// baseline (speedup 1.0000x reference)
#include <cuda_runtime.h>
#include <mma.h>
#include <cstdint>

#define Tdim 1024
#define Nb   32
#define Kdim 2048
#define Rdim 128
#define G    96
#define H    32
#define Sx   8

#define BK   32                  // K staged per pipeline step
#define CH   32                  // GRU chunk = GEMM tile rows per sample
#define NPAIR 16                 // samples processed in pairs (M=64)
#define NITEMS (32 * NPAIR)      // 32 t-chunks x 16 pairs
#define NBLK 148
#define NTHR 288                 // warps 0-7 GEMM, warp 8 GRU

// Scratch (device globals; no allocation in kernel_launch)
__device__ float g_Wct_hi[Kdim * G];   // tf32-hi of (W_ih@W_ann)^T, [k][g]
__device__ float g_Wct_lo[Kdim * G];   // fp32 residual, [k][g]
__device__ float g_bc[G];              // fused input bias (consumed in GRU)
__device__ float g_gx[Nb * Tdim * G];  // input projections (bias NOT included)
__device__ int   g_L[Nb];              // per-sample valid length (fea_len + 8)
__device__ int   g_work;               // GEMM work-queue head
__device__ int   g_flag[Nb * 32];      // ready flags, idx = c*Nb + n

// ---------------------------------------------------------------------------
__device__ __forceinline__ float tanhapx(float x) {
    float y;
    asm("tanh.approx.f32 %0, %1;" : "=f"(y) : "f"(x));
    return y;
}
__device__ __forceinline__ unsigned long long pk2(float a, float b) {
    unsigned long long r;
    asm("mov.b64 %0, {%1, %2};" : "=l"(r) : "f"(a), "f"(b));
    return r;
}
__device__ __forceinline__ void upk2(unsigned long long v, float& a, float& b) {
    asm("mov.b64 {%0, %1}, %2;" : "=f"(a), "=f"(b) : "l"(v));
}
#define FMA2(acc, a, b) asm("fma.rn.f32x2 %0, %1, %2, %0;" : "+l"(acc) : "l"(a), "l"(b))
#define ADD2(acc, b)    asm("add.rn.f32x2 %0, %0, %1;"     : "+l"(acc) : "l"(b))

__device__ __forceinline__ void cpasync16(uint32_t dst, const float* src) {
    asm volatile("cp.async.ca.shared.global [%0], [%1], 16;" :: "r"(dst), "l"(src));
}
#define BAR_GEMM() asm volatile("bar.sync 1, 256;" ::: "memory")

__device__ __forceinline__ float to_tf32(float x) {
    float y;
    asm("cvt.rna.tf32.f32 %0, %1;" : "=f"(y) : "f"(x));
    return y;
}

// ---------------------------------------------------------------------------
// PREP: fea_len decode (int32/int64 sniff) + queue/flag reset + fused weight
// W_ct = (W_ih @ W_ann), TRANSPOSED [k][g], split into tf32-hi + fp32 residual;
// bc = W_ih@b_ann + b_ih (consumed by the GRU bias path).
// grid (8 kblk, 12 gblk) x 256: thread owns k = bx*256+tid, 8 g's.
// ---------------------------------------------------------------------------
__global__ void prep_kernel(const int* __restrict__ fl,
                            const float* __restrict__ W_ann, const float* __restrict__ b_ann,
                            const float* __restrict__ W_ih,  const float* __restrict__ b_ih) {
    __shared__ float wih[8][Rdim];
    const int tid = threadIdx.x;
    const int g0  = blockIdx.y * 8;
    const int k   = blockIdx.x * 256 + tid;

    for (int i = tid; i < 8 * Rdim; i += 256)
        wih[i >> 7][i & 127] = W_ih[(g0 + (i >> 7)) * Rdim + (i & 127)];

    if (blockIdx.x == 0 && blockIdx.y == 0) {
        for (int i = tid; i < Nb * 32; i += 256) g_flag[i] = 0;
        if (tid == 0) {
            g_work = 0;
            // int64 little-endian => odd words are (all-zero) high words of
            // fea_len[0..15]; int32 => all-zero odd words prob ~(1/1016)^16.
            bool is64 = true;
            for (int i = 0; i < 16; ++i)
                if (fl[2 * i + 1] != 0) { is64 = false; break; }
            for (int n = 0; n < Nb; ++n)
                g_L[n] = (is64 ? fl[2 * n] : fl[n]) + Sx;
        }
    }
    __syncthreads();

    float acc[8];
#pragma unroll
    for (int g = 0; g < 8; ++g) acc[g] = 0.f;
    for (int r = 0; r < Rdim; ++r) {
        float wa = W_ann[(size_t)r * Kdim + k];
#pragma unroll
        for (int g = 0; g < 8; ++g) acc[g] = fmaf(wih[g][r], wa, acc[g]);
    }
#pragma unroll
    for (int g = 0; g < 8; ++g) {
        float hi = to_tf32(acc[g]);
        g_Wct_hi[(size_t)k * G + g0 + g] = hi;
        g_Wct_lo[(size_t)k * G + g0 + g] = acc[g] - hi;
    }

    if (blockIdx.x == 0 && tid < 8) {
        int g = g0 + tid;
        float b = b_ih[g];
        for (int r = 0; r < Rdim; ++r) b = fmaf(wih[tid][r], b_ann[r], b);
        g_bc[g] = b;
    }
}

// ---------------------------------------------------------------------------
// GRU step: halved-sum f32x2 packing, plain-layout h.
// Bias fold (CORRECT, from R10/R11): r/z input biases into gate bias (linear);
// n-gate input bias bcn stays on the x-side (folding into bn would get
// multiplied by r — the R8/R9 bug).
// ---------------------------------------------------------------------------
struct GruW {
    unsigned long long Wr2[H / 2], Wz2[H / 2], Wn2[H / 2];
    float br, bz, bn, bcn;
};

__device__ __forceinline__ void gru_step(const GruW& w,
                                         float xr, float xz, float xn,
                                         const float* hsR, float* hsW, int j,
                                         float& h, float& sumh) {
    const ulonglong2* hp = (const ulonglong2*)hsR;
    unsigned long long ar[4] = { pk2(w.br, 0.f), 0ull, 0ull, 0ull };
    unsigned long long az[4] = { pk2(w.bz, 0.f), 0ull, 0ull, 0ull };
    unsigned long long an[4] = { pk2(w.bn, 0.f), 0ull, 0ull, 0ull };
#pragma unroll
    for (int i = 0; i < 8; ++i) {
        ulonglong2 v = hp[i];
        FMA2(ar[(2 * i) & 3],     w.Wr2[2 * i],     v.x);
        FMA2(ar[(2 * i + 1) & 3], w.Wr2[2 * i + 1], v.y);
        FMA2(az[(2 * i) & 3],     w.Wz2[2 * i],     v.x);
        FMA2(az[(2 * i + 1) & 3], w.Wz2[2 * i + 1], v.y);
        FMA2(an[(2 * i) & 3],     w.Wn2[2 * i],     v.x);
        FMA2(an[(2 * i + 1) & 3], w.Wn2[2 * i + 1], v.y);
    }
    ADD2(ar[0], ar[1]); ADD2(ar[2], ar[3]); ADD2(ar[0], ar[2]);
    ADD2(az[0], az[1]); ADD2(az[2], az[3]); ADD2(az[0], az[2]);
    ADD2(an[0], an[1]); ADD2(an[2], an[3]); ADD2(an[0], an[2]);
    float lo, hi, arf, azf, anf;
    upk2(ar[0], lo, hi); arf = lo + hi;
    upk2(az[0], lo, hi); azf = lo + hi;
    upk2(an[0], lo, hi); anf = lo + hi;

    float r  = fmaf(0.5f, tanhapx(0.5f * (xr + arf)), 0.5f);  // sigmoid
    float z  = fmaf(0.5f, tanhapx(0.5f * (xz + azf)), 0.5f);
    float ng = tanhapx(fmaf(r, anf, xn + w.bcn));             // bc_n on x-side
    h = fmaf(z, h - ng, ng);   // (1-z)*ng + z*h
    sumh += h;

    hsW[j] = h;
    __syncwarp();
}

// ---------------------------------------------------------------------------
// Dynamic shared memory layout (16B-aligned fields).
// ---------------------------------------------------------------------------
struct Smem {
    float As[2][64][40];       // A tiles [m][k], pad 32->40
    float Bhi[2][BK][104];     // B tf32-hi [k][g], pad 96->104
    float Blo[2][BK][104];     // B residual [k][g]
    float xs[2][CH * G];       // GRU staged gx
    float hs[2][H];            // GRU hidden double buffer
    int   s_item;
};

// ---------------------------------------------------------------------------
// FUSED kernel. warps 0-7: tf32 wmma GEMM, 3xtf32 split (hi*hi + lo*hi +
// hi*lo; error ~2^-22), t-major queue of (t-chunk, sample-pair) items,
// M=64, N=96, cp.async double-buffered staging.
// warp 8 (blocks 0..31): GRU consumer (identical to R11's passing version).
// ---------------------------------------------------------------------------
__global__ void __launch_bounds__(NTHR, 1)
fused_kernel(const float* __restrict__ fea,
             const float* __restrict__ W_hh,
             const float* __restrict__ b_hh,
             const float* __restrict__ W_q,
             const float* __restrict__ b_q,
             float* __restrict__ out) {
    extern __shared__ __align__(16) unsigned char smem_raw[];
    Smem* sm = (Smem*)smem_raw;

    const int tid = threadIdx.x;

    if (tid < 256) {
        // ================= GEMM worker (tf32 wmma) =================
        using namespace nvcuda;
        const int w     = tid >> 5;
        const int mtile = w >> 1;       // rows 16*mtile..+15 of the 64-row tile
        const int nh    = w & 1;        // col half: cols 48*nh..+47 (3 x 16)

        for (;;) {
            if (tid == 0) sm->s_item = atomicAdd(&g_work, 1);
            BAR_GEMM();
            const int item = sm->s_item;
            BAR_GEMM();
            if (item >= NITEMS) break;
            const int c32 = item >> 4;          // t-major: low chunks first
            const int p   = item & 15;
            const int n0  = 2 * p, n1 = 2 * p + 1;
            const int t0  = c32 * CH;
            const int L0 = g_L[n0], L1 = g_L[n1];
            const int Lp = (L0 > L1) ? L0 : L1;
            if (t0 >= Lp) continue;             // dead pair-tile (uniform)

            // ---- staging (cp.async; 8 x 16B per thread per kt) ----
            auto stage = [&](int kt, int st) {
                // A: 64 rows x 32 k -> [m][k], 512 x 16B chunks
#pragma unroll
                for (int i = 0; i < 2; ++i) {
                    int ch = tid + i * 256;
                    int r = ch >> 3, q = ch & 7;
                    int nn = (r < 32) ? n0 : n1;
                    const float* src = fea + ((size_t)(nn * Tdim + t0 + (r & 31))) * Kdim
                                           + kt * BK + q * 4;
                    cpasync16((uint32_t)__cvta_generic_to_shared(&sm->As[st][r][q * 4]), src);
                }
                // B hi/lo: 32 k-rows x 96 g -> [k][g], 768 x 16B chunks each
#pragma unroll
                for (int i = 0; i < 3; ++i) {
                    int ch = tid + i * 256;
                    int kr = ch / 24, q = ch - kr * 24;
                    size_t off = (size_t)(kt * BK + kr) * G + q * 4;
                    cpasync16((uint32_t)__cvta_generic_to_shared(&sm->Bhi[st][kr][q * 4]),
                              g_Wct_hi + off);
                    cpasync16((uint32_t)__cvta_generic_to_shared(&sm->Blo[st][kr][q * 4]),
                              g_Wct_lo + off);
                }
                asm volatile("cp.async.commit_group;");
            };

            stage(0, 0);   // prologue

            wmma::fragment<wmma::accumulator, 16, 16, 8, float> acc[3];
#pragma unroll
            for (int c = 0; c < 3; ++c) wmma::fill_fragment(acc[c], 0.f);

            for (int kt = 0; kt < Kdim / BK; ++kt) {
                BAR_GEMM();                       // prev compute done before overwrite
                if (kt + 1 < Kdim / BK) {
                    stage(kt + 1, (kt + 1) & 1);
                    asm volatile("cp.async.wait_group 1;");
                } else {
                    asm volatile("cp.async.wait_group 0;");
                }
                BAR_GEMM();                       // stage kt visible to all

                const int st = kt & 1;
                const float* Ap = &sm->As[st][mtile * 16][0];
#pragma unroll
                for (int k8 = 0; k8 < 4; ++k8) {
                    wmma::fragment<wmma::matrix_a, 16, 16, 8, wmma::precision::tf32,
                                   wmma::row_major> af, ahi, alo;
                    wmma::load_matrix_sync(af, Ap + k8 * 8, 40);
#pragma unroll
                    for (int e = 0; e < af.num_elements; ++e) {
                        float x = af.x[e];
                        float hiv = to_tf32(x);
                        ahi.x[e] = hiv;
                        alo.x[e] = x - hiv;
                    }
#pragma unroll
                    for (int c = 0; c < 3; ++c) {
                        wmma::fragment<wmma::matrix_b, 16, 16, 8, wmma::precision::tf32,
                                       wmma::row_major> bh, bl;
                        wmma::load_matrix_sync(bh, &sm->Bhi[st][k8 * 8][nh * 48 + 16 * c], 104);
                        wmma::load_matrix_sync(bl, &sm->Blo[st][k8 * 8][nh * 48 + 16 * c], 104);
                        wmma::mma_sync(acc[c], ahi, bh, acc[c]);   // hi*hi
                        wmma::mma_sync(acc[c], alo, bh, acc[c]);   // lo*hi
                        wmma::mma_sync(acc[c], ahi, bl, acc[c]);   // hi*lo
                    }
                }
            }

            // ---- epilogue: store raw gx tile (biases handled in GRU) ----
            const int nn = (mtile < 2) ? n0 : n1;
            const int tr = t0 + (mtile & 1) * 16;
            float* gp = g_gx + ((size_t)(nn * Tdim + tr)) * G + nh * 48;
#pragma unroll
            for (int c = 0; c < 3; ++c)
                wmma::store_matrix_sync(gp + 16 * c, acc[c], G, wmma::mem_row_major);

            __threadfence();
            BAR_GEMM();
            if (tid == 0) {
                *(volatile int*)&g_flag[c32 * Nb + n0] = 1;
                *(volatile int*)&g_flag[c32 * Nb + n1] = 1;
            }
        }
        return;
    }

    // ================= GRU warp (warp 8) =================
    if (blockIdx.x >= Nb) return;
    const int n = blockIdx.x;
    const int j = tid & 31;
    const int L = g_L[n];                 // 8 <= L <= 1023
    const int nc = (L + CH - 1) / CH;

    GruW w;
    {
        const unsigned long long* wr = (const unsigned long long*)(W_hh + (0 * H + j) * H);
        const unsigned long long* wz = (const unsigned long long*)(W_hh + (1 * H + j) * H);
        const unsigned long long* wn = (const unsigned long long*)(W_hh + (2 * H + j) * H);
#pragma unroll
        for (int i = 0; i < H / 2; ++i) { w.Wr2[i] = wr[i]; w.Wz2[i] = wz[i]; w.Wn2[i] = wn[i]; }
    }
    w.br  = b_hh[j]         + g_bc[j];
    w.bz  = b_hh[H + j]     + g_bc[H + j];
    w.bn  = b_hh[2 * H + j];
    w.bcn = g_bc[2 * H + j];

    sm->hs[0][j] = 0.f;
    __syncwarp();

    const float* gx = g_gx + (size_t)n * Tdim * G;

    auto poll = [&](int c) {
        const volatile int* f = (const volatile int*)&g_flag[c * Nb + n];
        while (*f == 0) {}
        __threadfence();   // acquire
    };

    // stage chunk 0
    poll(0);
    {
        uint32_t dst = (uint32_t)__cvta_generic_to_shared(&sm->xs[0][0]);
#pragma unroll
        for (int i = 0; i < (CH * G) / (4 * 32); ++i)
            cpasync16(dst + (j + i * 32) * 16, gx + (j + i * 32) * 4);
        asm volatile("cp.async.commit_group;");
    }

    float h = 0.f, sumh = 0.f;
    int t = 0;
    for (int c = 0; c < nc; ++c) {
        if (c + 1 < nc) {
            poll(c + 1);
            uint32_t dst = (uint32_t)__cvta_generic_to_shared(&sm->xs[(c + 1) & 1][0]);
            const float* src = gx + (size_t)(c + 1) * CH * G;
#pragma unroll
            for (int i = 0; i < (CH * G) / (4 * 32); ++i)
                cpasync16(dst + (j + i * 32) * 16, src + (j + i * 32) * 4);
            asm volatile("cp.async.commit_group;");
            asm volatile("cp.async.wait_group 1;");
        } else {
            asm volatile("cp.async.wait_group 0;");
        }
        __syncwarp();

        const float* xb = sm->xs[c & 1];
        const int steps = (L - c * CH < CH) ? (L - c * CH) : CH;
        for (int s = 0; s < steps; ++s, ++t) {
            const float* xrow = xb + s * G;
            float xr = xrow[j], xz = xrow[H + j], xn = xrow[2 * H + j];
            const int par = t & 1;
            gru_step(w, xr, xz, xn, sm->hs[par], sm->hs[par ^ 1], j, h, sumh);
        }
    }

    // score[n] = (Wq . sum_t h)/L + b_q  (exact rearrangement)
    float s = sumh * W_q[j];
#pragma unroll
    for (int off = 16; off; off >>= 1) s += __shfl_xor_sync(0xffffffffu, s, off);
    if (j == 0) out[n] = s / (float)L + b_q[0];
}

// ---------------------------------------------------------------------------
extern "C" void kernel_launch(void* const* d_in, const int* in_sizes, int n_in,
                              void* d_out, int out_size) {
    (void)in_sizes; (void)n_in; (void)out_size;
    // metadata order: x, fea, fea_len, W_ann, b_ann, W_ih, W_hh, b_ih, b_hh, W_q, b_q
    const float* fea   = (const float*)d_in[1];
    const int*   fl    = (const int*)d_in[2];
    const float* W_ann = (const float*)d_in[3];
    const float* b_ann = (const float*)d_in[4];
    const float* W_ih  = (const float*)d_in[5];
    const float* W_hh  = (const float*)d_in[6];
    const float* b_ih  = (const float*)d_in[7];
    const float* b_hh  = (const float*)d_in[8];
    const float* W_q   = (const float*)d_in[9];
    const float* b_q   = (const float*)d_in[10];
    float*       out   = (float*)d_out;

    const int smem_bytes = (int)sizeof(Smem);
    cudaFuncSetAttribute(fused_kernel, cudaFuncAttributeMaxDynamicSharedMemorySize, smem_bytes);

    prep_kernel<<<dim3(8, 12), 256>>>(fl, W_ann, b_ann, W_ih, b_ih);
    fused_kernel<<<NBLK, NTHR, smem_bytes>>>(fea, W_hh, b_hh, W_q, b_q, out);
}

// round 13
// speedup vs baseline: 1.5303x; 1.5303x over previous
#include <cuda_runtime.h>
#include <cstdint>

#define Tdim 1024
#define Nb   32
#define Kdim 2048
#define Rdim 128
#define G    96
#define H    32
#define Sx   8

#define BK   32                  // K staged per pipeline step
#define CH   32                  // GRU chunk = GEMM tile rows per sample
#define NPAIR 16                 // samples processed in pairs (M=64)
#define NITEMS (32 * NPAIR)      // 32 t-chunks x 16 pairs
#define NBLK 148
#define NTHR 288                 // warps 0-7 GEMM, warp 8 GRU

// Scratch (device globals; no allocation in kernel_launch)
__device__ float g_Wct[Kdim * G];      // (W_ih@W_ann)^T, [k][g]  (full fp32)
__device__ float g_bc[G];              // fused input bias (consumed in GRU)
__device__ float g_gx[Nb * Tdim * G];  // input projections (bias NOT included)
__device__ int   g_L[Nb];              // per-sample valid length (fea_len + 8)
__device__ int   g_work;               // GEMM work-queue head
__device__ int   g_flag[Nb * 32];      // ready flags, idx = c*Nb + n

// ---------------------------------------------------------------------------
__device__ __forceinline__ float tanhapx(float x) {
    float y;
    asm("tanh.approx.f32 %0, %1;" : "=f"(y) : "f"(x));
    return y;
}
__device__ __forceinline__ unsigned long long pk2(float a, float b) {
    unsigned long long r;
    asm("mov.b64 %0, {%1, %2};" : "=l"(r) : "f"(a), "f"(b));
    return r;
}
__device__ __forceinline__ void upk2(unsigned long long v, float& a, float& b) {
    asm("mov.b64 {%0, %1}, %2;" : "=f"(a), "=f"(b) : "l"(v));
}
#define FMA2(acc, a, b) asm("fma.rn.f32x2 %0, %1, %2, %0;" : "+l"(acc) : "l"(a), "l"(b))
#define ADD2(acc, b)    asm("add.rn.f32x2 %0, %0, %1;"     : "+l"(acc) : "l"(b))

__device__ __forceinline__ void cpasync16(uint32_t dst, const float* src) {
    asm volatile("cp.async.ca.shared.global [%0], [%1], 16;" :: "r"(dst), "l"(src));
}
#define BAR_GEMM() asm volatile("bar.sync 1, 256;" ::: "memory")

// A-tile swizzle: row r (0..63) of 32 floats = 8 x 16B chunks; chunk c stored
// at slot (c ^ (r & 7)). Word offset: r*32 + ((c ^ (r&7)) << 2).
__device__ __forceinline__ int a_word(int r, int c) {
    return r * 32 + ((c ^ (r & 7)) << 2);
}

// ---------------------------------------------------------------------------
// PREP: fea_len decode (int32/int64 sniff) + queue/flag reset + fused weight
// W_ct = (W_ih @ W_ann) stored TRANSPOSED [k][g]; bc = W_ih@b_ann + b_ih.
// grid (8 kblk, 12 gblk) x 256: thread owns k = bx*256+tid, 8 g's.
// ---------------------------------------------------------------------------
__global__ void prep_kernel(const int* __restrict__ fl,
                            const float* __restrict__ W_ann, const float* __restrict__ b_ann,
                            const float* __restrict__ W_ih,  const float* __restrict__ b_ih) {
    __shared__ float wih[8][Rdim];
    const int tid = threadIdx.x;
    const int g0  = blockIdx.y * 8;
    const int k   = blockIdx.x * 256 + tid;

    for (int i = tid; i < 8 * Rdim; i += 256)
        wih[i >> 7][i & 127] = W_ih[(g0 + (i >> 7)) * Rdim + (i & 127)];

    if (blockIdx.x == 0 && blockIdx.y == 0) {
        for (int i = tid; i < Nb * 32; i += 256) g_flag[i] = 0;
        if (tid == 0) {
            g_work = 0;
            // int64 little-endian => odd words are (all-zero) high words of
            // fea_len[0..15]; int32 => all-zero odd words prob ~(1/1016)^16.
            bool is64 = true;
            for (int i = 0; i < 16; ++i)
                if (fl[2 * i + 1] != 0) { is64 = false; break; }
            for (int n = 0; n < Nb; ++n)
                g_L[n] = (is64 ? fl[2 * n] : fl[n]) + Sx;
        }
    }
    __syncthreads();

    float acc[8];
#pragma unroll
    for (int g = 0; g < 8; ++g) acc[g] = 0.f;
    for (int r = 0; r < Rdim; ++r) {
        float wa = W_ann[(size_t)r * Kdim + k];
#pragma unroll
        for (int g = 0; g < 8; ++g) acc[g] = fmaf(wih[g][r], wa, acc[g]);
    }
#pragma unroll
    for (int g = 0; g < 8; ++g)
        g_Wct[(size_t)k * G + g0 + g] = acc[g];

    if (blockIdx.x == 0 && tid < 8) {
        int g = g0 + tid;
        float b = b_ih[g];
        for (int r = 0; r < Rdim; ++r) b = fmaf(wih[tid][r], b_ann[r], b);
        g_bc[g] = b;
    }
}

// ---------------------------------------------------------------------------
// GRU step: halved-sum f32x2 packing, plain-layout h.
// Bias fold: r/z input biases into gate bias (linear); n-gate input bias bcn
// stays on the x-side (folding into bn would multiply it by r).
// ---------------------------------------------------------------------------
struct GruW {
    unsigned long long Wr2[H / 2], Wz2[H / 2], Wn2[H / 2];
    float br, bz, bn, bcn;
};

__device__ __forceinline__ void gru_step(const GruW& w,
                                         float xr, float xz, float xn,
                                         const float* hsR, float* hsW, int j,
                                         float& h, float& sumh) {
    const ulonglong2* hp = (const ulonglong2*)hsR;
    unsigned long long ar[4] = { pk2(w.br, 0.f), 0ull, 0ull, 0ull };
    unsigned long long az[4] = { pk2(w.bz, 0.f), 0ull, 0ull, 0ull };
    unsigned long long an[4] = { pk2(w.bn, 0.f), 0ull, 0ull, 0ull };
#pragma unroll
    for (int i = 0; i < 8; ++i) {
        ulonglong2 v = hp[i];
        FMA2(ar[(2 * i) & 3],     w.Wr2[2 * i],     v.x);
        FMA2(ar[(2 * i + 1) & 3], w.Wr2[2 * i + 1], v.y);
        FMA2(az[(2 * i) & 3],     w.Wz2[2 * i],     v.x);
        FMA2(az[(2 * i + 1) & 3], w.Wz2[2 * i + 1], v.y);
        FMA2(an[(2 * i) & 3],     w.Wn2[2 * i],     v.x);
        FMA2(an[(2 * i + 1) & 3], w.Wn2[2 * i + 1], v.y);
    }
    ADD2(ar[0], ar[1]); ADD2(ar[2], ar[3]); ADD2(ar[0], ar[2]);
    ADD2(az[0], az[1]); ADD2(az[2], az[3]); ADD2(az[0], az[2]);
    ADD2(an[0], an[1]); ADD2(an[2], an[3]); ADD2(an[0], an[2]);
    float lo, hi, arf, azf, anf;
    upk2(ar[0], lo, hi); arf = lo + hi;
    upk2(az[0], lo, hi); azf = lo + hi;
    upk2(an[0], lo, hi); anf = lo + hi;

    float r  = fmaf(0.5f, tanhapx(0.5f * (xr + arf)), 0.5f);  // sigmoid
    float z  = fmaf(0.5f, tanhapx(0.5f * (xz + azf)), 0.5f);
    float ng = tanhapx(fmaf(r, anf, xn + w.bcn));             // bc_n on x-side
    h = fmaf(z, h - ng, ng);   // (1-z)*ng + z*h
    sumh += h;

    hsW[j] = h;
    __syncwarp();
}

// ---------------------------------------------------------------------------
// Dynamic shared memory layout (16B-aligned fields).
// ---------------------------------------------------------------------------
struct Smem {
    float As[2][64 * 32];      // A tiles, XOR-swizzled 16B chunks (see a_word)
    float Bs[2][BK][104];      // B [k][g], pad 96->104
    float xs[2][CH * G];       // GRU staged gx
    float hs[2][H];            // GRU hidden double buffer
    int   s_item;
};

// ---------------------------------------------------------------------------
// FUSED kernel. warps 0-7: scalar f32x2 GEMM, t-major queue of (t-chunk,
// sample-pair) items, M=64, N=96, cp.async double-buffered staging.
// Inner loop FULLY UNROLLED with register software-pipelining: B for k+1 and
// the A 4-group for k4+1 are loaded while FMAing step k, so LDS latency
// (29cyc) is hidden behind >=12 FMA2 of slack (R11 exposed it: issue 43.7%).
// warp 8 (blocks 0..31): GRU consumer.
// ---------------------------------------------------------------------------
__global__ void __launch_bounds__(NTHR, 1)
fused_kernel(const float* __restrict__ fea,
             const float* __restrict__ W_hh,
             const float* __restrict__ b_hh,
             const float* __restrict__ W_q,
             const float* __restrict__ b_q,
             float* __restrict__ out) {
    extern __shared__ __align__(16) unsigned char smem_raw[];
    Smem* sm = (Smem*)smem_raw;

    const int tid = threadIdx.x;

    if (tid < 256) {
        // ================= GEMM worker (scalar f32x2, pipelined) ==========
        const int tx = tid & 15;     // rows tx, tx+16, tx+32, tx+48
        const int ty = tid >> 4;     // cols 6ty..6ty+5 (3 pairs)

        for (;;) {
            if (tid == 0) sm->s_item = atomicAdd(&g_work, 1);
            BAR_GEMM();
            const int item = sm->s_item;
            BAR_GEMM();
            if (item >= NITEMS) break;
            const int c32 = item >> 4;          // t-major: low chunks first
            const int p   = item & 15;
            const int n0  = 2 * p, n1 = 2 * p + 1;
            const int t0  = c32 * CH;
            const int L0 = g_L[n0], L1 = g_L[n1];
            const int Lp = (L0 > L1) ? L0 : L1;
            if (t0 >= Lp) continue;             // dead pair-tile (uniform)

            // ---- staging (cp.async; 5 x 16B per thread per kt) ----
            auto stage = [&](int kt, int st) {
#pragma unroll
                for (int i = 0; i < 2; ++i) {
                    int ch = tid + i * 256;
                    int r = ch >> 3, q = ch & 7;
                    int nn = (r < 32) ? n0 : n1;
                    const float* src = fea + ((size_t)(nn * Tdim + t0 + (r & 31))) * Kdim
                                           + kt * BK + q * 4;
                    cpasync16((uint32_t)__cvta_generic_to_shared(&sm->As[st][a_word(r, q)]),
                              src);
                }
#pragma unroll
                for (int i = 0; i < 3; ++i) {
                    int ch = tid + i * 256;
                    int kr = ch / 24, q = ch - kr * 24;
                    cpasync16((uint32_t)__cvta_generic_to_shared(&sm->Bs[st][kr][q * 4]),
                              g_Wct + (size_t)(kt * BK + kr) * G + q * 4);
                }
                asm volatile("cp.async.commit_group;");
            };

            stage(0, 0);   // prologue

            unsigned long long acc[4][3];
#pragma unroll
            for (int i = 0; i < 4; ++i)
#pragma unroll
                for (int q = 0; q < 3; ++q) acc[i][q] = 0ull;

            for (int kt = 0; kt < Kdim / BK; ++kt) {
                BAR_GEMM();                       // prev compute done before overwrite
                if (kt + 1 < Kdim / BK) {
                    stage(kt + 1, (kt + 1) & 1);
                    asm volatile("cp.async.wait_group 1;");
                } else {
                    asm volatile("cp.async.wait_group 0;");
                }
                BAR_GEMM();                       // stage kt visible to all

                const int st = kt & 1;

                // ---- fully-unrolled software-pipelined stage compute ----
                float4 a[4], an[4];
#pragma unroll
                for (int i = 0; i < 4; ++i)
                    a[i] = *(const float4*)&sm->As[st][a_word(tx + 16 * i, 0)];
                unsigned long long b[3], bn[3];
#pragma unroll
                for (int q = 0; q < 3; ++q)
                    b[q] = *(const unsigned long long*)&sm->Bs[st][0][6 * ty + 2 * q];

#pragma unroll
                for (int k = 0; k < BK; ++k) {
                    // prefetch B for k+1
                    if (k + 1 < BK) {
#pragma unroll
                        for (int q = 0; q < 3; ++q)
                            bn[q] = *(const unsigned long long*)
                                        &sm->Bs[st][k + 1][6 * ty + 2 * q];
                    }
                    // prefetch A 4-group for the next k4 block, early
                    if ((k & 3) == 0 && k + 4 < BK) {
#pragma unroll
                        for (int i = 0; i < 4; ++i)
                            an[i] = *(const float4*)
                                        &sm->As[st][a_word(tx + 16 * i, (k >> 2) + 1)];
                    }
#pragma unroll
                    for (int i = 0; i < 4; ++i) {
                        const float av = ((k & 3) == 0) ? a[i].x
                                       : ((k & 3) == 1) ? a[i].y
                                       : ((k & 3) == 2) ? a[i].z : a[i].w;
                        unsigned long long d = pk2(av, av);
#pragma unroll
                        for (int q = 0; q < 3; ++q)
                            FMA2(acc[i][q], d, b[q]);
                    }
                    // rotate (rename-free in unrolled SSA)
                    if (k + 1 < BK) {
#pragma unroll
                        for (int q = 0; q < 3; ++q) b[q] = bn[q];
                    }
                    if ((k & 3) == 3 && k + 1 < BK) {
#pragma unroll
                        for (int i = 0; i < 4; ++i) a[i] = an[i];
                    }
                }
            }

            // ---- epilogue: store raw gx tile (biases handled in GRU) ----
#pragma unroll
            for (int i = 0; i < 4; ++i) {
                const int r  = tx + 16 * i;
                const int nn = (r < 32) ? n0 : n1;
                float* gp = g_gx + ((size_t)(nn * Tdim + t0 + (r & 31))) * G + 6 * ty;
#pragma unroll
                for (int q = 0; q < 3; ++q) {
                    float lo, hi;
                    upk2(acc[i][q], lo, hi);
                    *(float2*)&gp[2 * q] = make_float2(lo, hi);
                }
            }

            __threadfence();
            BAR_GEMM();
            if (tid == 0) {
                *(volatile int*)&g_flag[c32 * Nb + n0] = 1;
                *(volatile int*)&g_flag[c32 * Nb + n1] = 1;
            }
        }
        return;
    }

    // ================= GRU warp (warp 8) =================
    if (blockIdx.x >= Nb) return;
    const int n = blockIdx.x;
    const int j = tid & 31;
    const int L = g_L[n];                 // 8 <= L <= 1023
    const int nc = (L + CH - 1) / CH;

    GruW w;
    {
        const unsigned long long* wr = (const unsigned long long*)(W_hh + (0 * H + j) * H);
        const unsigned long long* wz = (const unsigned long long*)(W_hh + (1 * H + j) * H);
        const unsigned long long* wn = (const unsigned long long*)(W_hh + (2 * H + j) * H);
#pragma unroll
        for (int i = 0; i < H / 2; ++i) { w.Wr2[i] = wr[i]; w.Wz2[i] = wz[i]; w.Wn2[i] = wn[i]; }
    }
    w.br  = b_hh[j]         + g_bc[j];
    w.bz  = b_hh[H + j]     + g_bc[H + j];
    w.bn  = b_hh[2 * H + j];
    w.bcn = g_bc[2 * H + j];

    sm->hs[0][j] = 0.f;
    __syncwarp();

    const float* gx = g_gx + (size_t)n * Tdim * G;

    auto poll = [&](int c) {
        const volatile int* f = (const volatile int*)&g_flag[c * Nb + n];
        while (*f == 0) {}
        __threadfence();   // acquire
    };

    // stage chunk 0
    poll(0);
    {
        uint32_t dst = (uint32_t)__cvta_generic_to_shared(&sm->xs[0][0]);
#pragma unroll
        for (int i = 0; i < (CH * G) / (4 * 32); ++i)
            cpasync16(dst + (j + i * 32) * 16, gx + (j + i * 32) * 4);
        asm volatile("cp.async.commit_group;");
    }

    float h = 0.f, sumh = 0.f;
    int t = 0;
    for (int c = 0; c < nc; ++c) {
        if (c + 1 < nc) {
            poll(c + 1);
            uint32_t dst = (uint32_t)__cvta_generic_to_shared(&sm->xs[(c + 1) & 1][0]);
            const float* src = gx + (size_t)(c + 1) * CH * G;
#pragma unroll
            for (int i = 0; i < (CH * G) / (4 * 32); ++i)
                cpasync16(dst + (j + i * 32) * 16, src + (j + i * 32) * 4);
            asm volatile("cp.async.commit_group;");
            asm volatile("cp.async.wait_group 1;");
        } else {
            asm volatile("cp.async.wait_group 0;");
        }
        __syncwarp();

        const float* xb = sm->xs[c & 1];
        const int steps = (L - c * CH < CH) ? (L - c * CH) : CH;
        for (int s = 0; s < steps; ++s, ++t) {
            const float* xrow = xb + s * G;
            float xr = xrow[j], xz = xrow[H + j], xn = xrow[2 * H + j];
            const int par = t & 1;
            gru_step(w, xr, xz, xn, sm->hs[par], sm->hs[par ^ 1], j, h, sumh);
        }
    }

    // score[n] = (Wq . sum_t h)/L + b_q  (exact rearrangement)
    float s = sumh * W_q[j];
#pragma unroll
    for (int off = 16; off; off >>= 1) s += __shfl_xor_sync(0xffffffffu, s, off);
    if (j == 0) out[n] = s / (float)L + b_q[0];
}

// ---------------------------------------------------------------------------
extern "C" void kernel_launch(void* const* d_in, const int* in_sizes, int n_in,
                              void* d_out, int out_size) {
    (void)in_sizes; (void)n_in; (void)out_size;
    // metadata order: x, fea, fea_len, W_ann, b_ann, W_ih, W_hh, b_ih, b_hh, W_q, b_q
    const float* fea   = (const float*)d_in[1];
    const int*   fl    = (const int*)d_in[2];
    const float* W_ann = (const float*)d_in[3];
    const float* b_ann = (const float*)d_in[4];
    const float* W_ih  = (const float*)d_in[5];
    const float* W_hh  = (const float*)d_in[6];
    const float* b_ih  = (const float*)d_in[7];
    const float* b_hh  = (const float*)d_in[8];
    const float* W_q   = (const float*)d_in[9];
    const float* b_q   = (const float*)d_in[10];
    float*       out   = (float*)d_out;

    const int smem_bytes = (int)sizeof(Smem);
    cudaFuncSetAttribute(fused_kernel, cudaFuncAttributeMaxDynamicSharedMemorySize, smem_bytes);

    prep_kernel<<<dim3(8, 12), 256>>>(fl, W_ann, b_ann, W_ih, b_ih);
    fused_kernel<<<NBLK, NTHR, smem_bytes>>>(fea, W_hh, b_hh, W_q, b_q, out);
}

// round 14
// speedup vs baseline: 1.5734x; 1.0282x over previous
#include <cuda_runtime.h>
#include <cstdint>

#define Tdim 1024
#define Nb   32
#define Kdim 2048
#define Rdim 128
#define G    96
#define H    32
#define Sx   8

#define BK   32                  // K staged per pipeline step
#define CH   32                  // GRU chunk = GEMM tile rows per sample
#define NPAIR 16                 // samples processed in pairs (M=64)
#define NITEMS (32 * NPAIR)      // 32 t-chunks x 16 pairs
#define NBLK 148
#define NTHR 288                 // warps 0-7 GEMM, warp 8 GRU

// Scratch (device globals; no allocation in kernel_launch)
__device__ float g_Wct[Kdim * G];      // (W_ih@W_ann)^T, [k][g]  (full fp32)
__device__ float g_bc[G];              // fused input bias (consumed in GRU)
__device__ float g_gx[Nb * Tdim * G];  // input projections (bias NOT included)
__device__ int   g_L[Nb];              // per-sample valid length (fea_len + 8)
__device__ int   g_perm[Nb];           // samples sorted by L (pairing map)
__device__ int   g_work;               // GEMM work-queue head
__device__ int   g_flag[Nb * 32];      // ready flags, idx = c*Nb + n

// ---------------------------------------------------------------------------
__device__ __forceinline__ float tanhapx(float x) {
    float y;
    asm("tanh.approx.f32 %0, %1;" : "=f"(y) : "f"(x));
    return y;
}
__device__ __forceinline__ unsigned long long pk2(float a, float b) {
    unsigned long long r;
    asm("mov.b64 %0, {%1, %2};" : "=l"(r) : "f"(a), "f"(b));
    return r;
}
__device__ __forceinline__ void upk2(unsigned long long v, float& a, float& b) {
    asm("mov.b64 {%0, %1}, %2;" : "=f"(a), "=f"(b) : "l"(v));
}
#define FMA2(acc, a, b) asm("fma.rn.f32x2 %0, %1, %2, %0;" : "+l"(acc) : "l"(a), "l"(b))
#define ADD2(acc, b)    asm("add.rn.f32x2 %0, %0, %1;"     : "+l"(acc) : "l"(b))

__device__ __forceinline__ void cpasync16(uint32_t dst, const float* src) {
    asm volatile("cp.async.ca.shared.global [%0], [%1], 16;" :: "r"(dst), "l"(src));
}
#define BAR_GEMM() asm volatile("bar.sync 1, 256;" ::: "memory")

// A-tile swizzle: row r (0..63) of 32 floats = 8 x 16B chunks; chunk c stored
// at slot (c ^ (r & 7)). Word offset: r*32 + ((c ^ (r&7)) << 2).
__device__ __forceinline__ int a_word(int r, int c) {
    return r * 32 + ((c ^ (r & 7)) << 2);
}

// ---------------------------------------------------------------------------
// PREP: fea_len decode (int32/int64 sniff) + queue/flag reset + length-sorted
// pairing permutation + fused weight W_ct = (W_ih@W_ann)^T [k][g] and
// bc = W_ih@b_ann + b_ih.
// grid (8 kblk, 12 gblk) x 256: thread owns k = bx*256+tid, 8 g's.
// ---------------------------------------------------------------------------
__global__ void prep_kernel(const int* __restrict__ fl,
                            const float* __restrict__ W_ann, const float* __restrict__ b_ann,
                            const float* __restrict__ W_ih,  const float* __restrict__ b_ih) {
    __shared__ float wih[8][Rdim];
    const int tid = threadIdx.x;
    const int g0  = blockIdx.y * 8;
    const int k   = blockIdx.x * 256 + tid;

    for (int i = tid; i < 8 * Rdim; i += 256)
        wih[i >> 7][i & 127] = W_ih[(g0 + (i >> 7)) * Rdim + (i & 127)];

    if (blockIdx.x == 0 && blockIdx.y == 0) {
        for (int i = tid; i < Nb * 32; i += 256) g_flag[i] = 0;
        if (tid == 0) {
            g_work = 0;
            // int64 little-endian => odd words are (all-zero) high words of
            // fea_len[0..15]; int32 => all-zero odd words prob ~(1/1016)^16.
            bool is64 = true;
            for (int i = 0; i < 16; ++i)
                if (fl[2 * i + 1] != 0) { is64 = false; break; }
            int Ls[Nb], idx[Nb];
            for (int n = 0; n < Nb; ++n) {
                Ls[n] = (is64 ? fl[2 * n] : fl[n]) + Sx;
                g_L[n] = Ls[n];
                idx[n] = n;
            }
            // insertion sort by L ascending -> rank-adjacent pairing minimizes
            // per-pair waste E[max(L0,L1) - min(L0,L1)] (was ~339 rows, now ~30)
            for (int a = 1; a < Nb; ++a) {
                int vi = idx[a], vl = Ls[vi];
                int bpos = a - 1;
                while (bpos >= 0 && Ls[idx[bpos]] > vl) {
                    idx[bpos + 1] = idx[bpos];
                    --bpos;
                }
                idx[bpos + 1] = vi;
            }
            for (int n = 0; n < Nb; ++n) g_perm[n] = idx[n];
        }
    }
    __syncthreads();

    float acc[8];
#pragma unroll
    for (int g = 0; g < 8; ++g) acc[g] = 0.f;
    for (int r = 0; r < Rdim; ++r) {
        float wa = W_ann[(size_t)r * Kdim + k];
#pragma unroll
        for (int g = 0; g < 8; ++g) acc[g] = fmaf(wih[g][r], wa, acc[g]);
    }
#pragma unroll
    for (int g = 0; g < 8; ++g)
        g_Wct[(size_t)k * G + g0 + g] = acc[g];

    if (blockIdx.x == 0 && tid < 8) {
        int g = g0 + tid;
        float b = b_ih[g];
        for (int r = 0; r < Rdim; ++r) b = fmaf(wih[tid][r], b_ann[r], b);
        g_bc[g] = b;
    }
}

// ---------------------------------------------------------------------------
// GRU step: halved-sum f32x2 packing, plain-layout h.
// Bias fold: r/z input biases into gate bias (linear); n-gate input bias bcn
// stays on the x-side (folding into bn would multiply it by r).
// ---------------------------------------------------------------------------
struct GruW {
    unsigned long long Wr2[H / 2], Wz2[H / 2], Wn2[H / 2];
    float br, bz, bn, bcn;
};

__device__ __forceinline__ void gru_step(const GruW& w,
                                         float xr, float xz, float xn,
                                         const float* hsR, float* hsW, int j,
                                         float& h, float& sumh) {
    const ulonglong2* hp = (const ulonglong2*)hsR;
    unsigned long long ar[4] = { pk2(w.br, 0.f), 0ull, 0ull, 0ull };
    unsigned long long az[4] = { pk2(w.bz, 0.f), 0ull, 0ull, 0ull };
    unsigned long long an[4] = { pk2(w.bn, 0.f), 0ull, 0ull, 0ull };
#pragma unroll
    for (int i = 0; i < 8; ++i) {
        ulonglong2 v = hp[i];
        FMA2(ar[(2 * i) & 3],     w.Wr2[2 * i],     v.x);
        FMA2(ar[(2 * i + 1) & 3], w.Wr2[2 * i + 1], v.y);
        FMA2(az[(2 * i) & 3],     w.Wz2[2 * i],     v.x);
        FMA2(az[(2 * i + 1) & 3], w.Wz2[2 * i + 1], v.y);
        FMA2(an[(2 * i) & 3],     w.Wn2[2 * i],     v.x);
        FMA2(an[(2 * i + 1) & 3], w.Wn2[2 * i + 1], v.y);
    }
    ADD2(ar[0], ar[1]); ADD2(ar[2], ar[3]); ADD2(ar[0], ar[2]);
    ADD2(az[0], az[1]); ADD2(az[2], az[3]); ADD2(az[0], az[2]);
    ADD2(an[0], an[1]); ADD2(an[2], an[3]); ADD2(an[0], an[2]);
    float lo, hi, arf, azf, anf;
    upk2(ar[0], lo, hi); arf = lo + hi;
    upk2(az[0], lo, hi); azf = lo + hi;
    upk2(an[0], lo, hi); anf = lo + hi;

    float r  = fmaf(0.5f, tanhapx(0.5f * (xr + arf)), 0.5f);  // sigmoid
    float z  = fmaf(0.5f, tanhapx(0.5f * (xz + azf)), 0.5f);
    float ng = tanhapx(fmaf(r, anf, xn + w.bcn));             // bc_n on x-side
    h = fmaf(z, h - ng, ng);   // (1-z)*ng + z*h
    sumh += h;

    hsW[j] = h;
    __syncwarp();
}

// ---------------------------------------------------------------------------
// Dynamic shared memory layout (16B-aligned fields).
// ---------------------------------------------------------------------------
struct Smem {
    float As[2][64 * 32];      // A tiles, XOR-swizzled 16B chunks (see a_word)
    float Bs[2][BK][104];      // B [k][g], pad 96->104
    float xs[2][CH * G];       // GRU staged gx
    float hs[2][H];            // GRU hidden double buffer
    int   s_item;
};

// ---------------------------------------------------------------------------
// FUSED kernel. warps 0-7: scalar f32x2 GEMM, t-major queue of (t-chunk,
// sorted-sample-pair) items, M=64, N=96, cp.async double-buffered staging.
// warp 8 (blocks 0..31): GRU consumer.
// ---------------------------------------------------------------------------
__global__ void __launch_bounds__(NTHR, 1)
fused_kernel(const float* __restrict__ fea,
             const float* __restrict__ W_hh,
             const float* __restrict__ b_hh,
             const float* __restrict__ W_q,
             const float* __restrict__ b_q,
             float* __restrict__ out) {
    extern __shared__ __align__(16) unsigned char smem_raw[];
    Smem* sm = (Smem*)smem_raw;

    const int tid = threadIdx.x;

    if (tid < 256) {
        // ================= GEMM worker (scalar f32x2, pipelined) ==========
        const int tx = tid & 15;     // rows tx, tx+16, tx+32, tx+48
        const int ty = tid >> 4;     // cols 6ty..6ty+5 (3 pairs)

        for (;;) {
            if (tid == 0) sm->s_item = atomicAdd(&g_work, 1);
            BAR_GEMM();
            const int item = sm->s_item;
            BAR_GEMM();
            if (item >= NITEMS) break;
            const int c32 = item >> 4;          // t-major: low chunks first
            const int p   = item & 15;
            const int n0  = g_perm[2 * p];      // length-sorted pairing
            const int n1  = g_perm[2 * p + 1];
            const int t0  = c32 * CH;
            const int L0 = g_L[n0], L1 = g_L[n1];
            const int Lp = (L0 > L1) ? L0 : L1;
            if (t0 >= Lp) continue;             // dead pair-tile (uniform)

            // ---- staging (cp.async; 5 x 16B per thread per kt) ----
            auto stage = [&](int kt, int st) {
#pragma unroll
                for (int i = 0; i < 2; ++i) {
                    int ch = tid + i * 256;
                    int r = ch >> 3, q = ch & 7;
                    int nn = (r < 32) ? n0 : n1;
                    const float* src = fea + ((size_t)(nn * Tdim + t0 + (r & 31))) * Kdim
                                           + kt * BK + q * 4;
                    cpasync16((uint32_t)__cvta_generic_to_shared(&sm->As[st][a_word(r, q)]),
                              src);
                }
#pragma unroll
                for (int i = 0; i < 3; ++i) {
                    int ch = tid + i * 256;
                    int kr = ch / 24, q = ch - kr * 24;
                    cpasync16((uint32_t)__cvta_generic_to_shared(&sm->Bs[st][kr][q * 4]),
                              g_Wct + (size_t)(kt * BK + kr) * G + q * 4);
                }
                asm volatile("cp.async.commit_group;");
            };

            stage(0, 0);   // prologue

            unsigned long long acc[4][3];
#pragma unroll
            for (int i = 0; i < 4; ++i)
#pragma unroll
                for (int q = 0; q < 3; ++q) acc[i][q] = 0ull;

            for (int kt = 0; kt < Kdim / BK; ++kt) {
                BAR_GEMM();                       // prev compute done before overwrite
                if (kt + 1 < Kdim / BK) {
                    stage(kt + 1, (kt + 1) & 1);
                    asm volatile("cp.async.wait_group 1;");
                } else {
                    asm volatile("cp.async.wait_group 0;");
                }
                BAR_GEMM();                       // stage kt visible to all

                const int st = kt & 1;

                float4 a[4], an[4];
#pragma unroll
                for (int i = 0; i < 4; ++i)
                    a[i] = *(const float4*)&sm->As[st][a_word(tx + 16 * i, 0)];
                unsigned long long b[3], bn[3];
#pragma unroll
                for (int q = 0; q < 3; ++q)
                    b[q] = *(const unsigned long long*)&sm->Bs[st][0][6 * ty + 2 * q];

#pragma unroll
                for (int k = 0; k < BK; ++k) {
                    if (k + 1 < BK) {
#pragma unroll
                        for (int q = 0; q < 3; ++q)
                            bn[q] = *(const unsigned long long*)
                                        &sm->Bs[st][k + 1][6 * ty + 2 * q];
                    }
                    if ((k & 3) == 0 && k + 4 < BK) {
#pragma unroll
                        for (int i = 0; i < 4; ++i)
                            an[i] = *(const float4*)
                                        &sm->As[st][a_word(tx + 16 * i, (k >> 2) + 1)];
                    }
#pragma unroll
                    for (int i = 0; i < 4; ++i) {
                        const float av = ((k & 3) == 0) ? a[i].x
                                       : ((k & 3) == 1) ? a[i].y
                                       : ((k & 3) == 2) ? a[i].z : a[i].w;
                        unsigned long long d = pk2(av, av);
#pragma unroll
                        for (int q = 0; q < 3; ++q)
                            FMA2(acc[i][q], d, b[q]);
                    }
                    if (k + 1 < BK) {
#pragma unroll
                        for (int q = 0; q < 3; ++q) b[q] = bn[q];
                    }
                    if ((k & 3) == 3 && k + 1 < BK) {
#pragma unroll
                        for (int i = 0; i < 4; ++i) a[i] = an[i];
                    }
                }
            }

            // ---- epilogue: store raw gx tile (biases handled in GRU) ----
#pragma unroll
            for (int i = 0; i < 4; ++i) {
                const int r  = tx + 16 * i;
                const int nn = (r < 32) ? n0 : n1;
                float* gp = g_gx + ((size_t)(nn * Tdim + t0 + (r & 31))) * G + 6 * ty;
#pragma unroll
                for (int q = 0; q < 3; ++q) {
                    float lo, hi;
                    upk2(acc[i][q], lo, hi);
                    *(float2*)&gp[2 * q] = make_float2(lo, hi);
                }
            }

            __threadfence();
            BAR_GEMM();
            if (tid == 0) {
                *(volatile int*)&g_flag[c32 * Nb + n0] = 1;
                *(volatile int*)&g_flag[c32 * Nb + n1] = 1;
            }
        }
        return;
    }

    // ================= GRU warp (warp 8) =================
    if (blockIdx.x >= Nb) return;
    const int n = blockIdx.x;
    const int j = tid & 31;
    const int L = g_L[n];                 // 8 <= L <= 1023
    const int nc = (L + CH - 1) / CH;

    GruW w;
    {
        const unsigned long long* wr = (const unsigned long long*)(W_hh + (0 * H + j) * H);
        const unsigned long long* wz = (const unsigned long long*)(W_hh + (1 * H + j) * H);
        const unsigned long long* wn = (const unsigned long long*)(W_hh + (2 * H + j) * H);
#pragma unroll
        for (int i = 0; i < H / 2; ++i) { w.Wr2[i] = wr[i]; w.Wz2[i] = wz[i]; w.Wn2[i] = wn[i]; }
    }
    w.br  = b_hh[j]         + g_bc[j];
    w.bz  = b_hh[H + j]     + g_bc[H + j];
    w.bn  = b_hh[2 * H + j];
    w.bcn = g_bc[2 * H + j];

    sm->hs[0][j] = 0.f;
    __syncwarp();

    const float* gx = g_gx + (size_t)n * Tdim * G;

    auto poll = [&](int c) {
        const volatile int* f = (const volatile int*)&g_flag[c * Nb + n];
        while (*f == 0) {}
        __threadfence();   // acquire
    };

    // stage chunk 0
    poll(0);
    {
        uint32_t dst = (uint32_t)__cvta_generic_to_shared(&sm->xs[0][0]);
#pragma unroll
        for (int i = 0; i < (CH * G) / (4 * 32); ++i)
            cpasync16(dst + (j + i * 32) * 16, gx + (j + i * 32) * 4);
        asm volatile("cp.async.commit_group;");
    }

    float h = 0.f, sumh = 0.f;
    int t = 0;
    for (int c = 0; c < nc; ++c) {
        if (c + 1 < nc) {
            poll(c + 1);
            uint32_t dst = (uint32_t)__cvta_generic_to_shared(&sm->xs[(c + 1) & 1][0]);
            const float* src = gx + (size_t)(c + 1) * CH * G;
#pragma unroll
            for (int i = 0; i < (CH * G) / (4 * 32); ++i)
                cpasync16(dst + (j + i * 32) * 16, src + (j + i * 32) * 4);
            asm volatile("cp.async.commit_group;");
            asm volatile("cp.async.wait_group 1;");
        } else {
            asm volatile("cp.async.wait_group 0;");
        }
        __syncwarp();

        const float* xb = sm->xs[c & 1];
        const int steps = (L - c * CH < CH) ? (L - c * CH) : CH;
        for (int s = 0; s < steps; ++s, ++t) {
            const float* xrow = xb + s * G;
            float xr = xrow[j], xz = xrow[H + j], xn = xrow[2 * H + j];
            const int par = t & 1;
            gru_step(w, xr, xz, xn, sm->hs[par], sm->hs[par ^ 1], j, h, sumh);
        }
    }

    // score[n] = (Wq . sum_t h)/L + b_q  (exact rearrangement)
    float s = sumh * W_q[j];
#pragma unroll
    for (int off = 16; off; off >>= 1) s += __shfl_xor_sync(0xffffffffu, s, off);
    if (j == 0) out[n] = s / (float)L + b_q[0];
}

// ---------------------------------------------------------------------------
extern "C" void kernel_launch(void* const* d_in, const int* in_sizes, int n_in,
                              void* d_out, int out_size) {
    (void)in_sizes; (void)n_in; (void)out_size;
    // metadata order: x, fea, fea_len, W_ann, b_ann, W_ih, W_hh, b_ih, b_hh, W_q, b_q
    const float* fea   = (const float*)d_in[1];
    const int*   fl    = (const int*)d_in[2];
    const float* W_ann = (const float*)d_in[3];
    const float* b_ann = (const float*)d_in[4];
    const float* W_ih  = (const float*)d_in[5];
    const float* W_hh  = (const float*)d_in[6];
    const float* b_ih  = (const float*)d_in[7];
    const float* b_hh  = (const float*)d_in[8];
    const float* W_q   = (const float*)d_in[9];
    const float* b_q   = (const float*)d_in[10];
    float*       out   = (float*)d_out;

    const int smem_bytes = (int)sizeof(Smem);
    cudaFuncSetAttribute(fused_kernel, cudaFuncAttributeMaxDynamicSharedMemorySize, smem_bytes);

    prep_kernel<<<dim3(8, 12), 256>>>(fl, W_ann, b_ann, W_ih, b_ih);
    fused_kernel<<<NBLK, NTHR, smem_bytes>>>(fea, W_hh, b_hh, W_q, b_q, out);
}